// round 10
// baseline (speedup 1.0000x reference)
#include <cuda_runtime.h>
#include <math.h>

#define T_DIM 2048
#define C_DIM 512
#define NB 4
#define BATCH 2
#define HALF_C 256
#define SCALE 0.044194173824159216f
#define NEGINF -1e30f

#define QT 32
#define ST 64
#define UPB 288
#define UNITS (BATCH * UPB)  // 576

typedef unsigned long long ull;

__device__ float g_q[BATCH * NB * T_DIM * C_DIM];
__device__ float g_v[BATCH * NB * T_DIM * C_DIM];
__device__ float g_k[BATCH * T_DIM * C_DIM];
__device__ float g_y[BATCH * T_DIM * C_DIM];
__device__ float g_ypart[(size_t)UNITS * QT * C_DIM];
__device__ float g_mpart[UNITS * QT];
__device__ float g_lpart[UNITS * QT];

// ---- f32x2 packed helpers (sm_103a FFMA2 path, PTX-only) ----
__device__ __forceinline__ ull pk2(float v) {
    ull r; asm("mov.b64 %0, {%1, %1};" : "=l"(r) : "f"(v)); return r;
}
__device__ __forceinline__ void upk2(ull v, float& lo, float& hi) {
    asm("mov.b64 {%0, %1}, %2;" : "=f"(lo), "=f"(hi) : "l"(v));
}
__device__ __forceinline__ ull ffma2(ull a, ull b, ull c) {
    ull d; asm("fma.rn.f32x2 %0, %1, %2, %3;" : "=l"(d) : "l"(a), "l"(b), "l"(c));
    return d;
}
__device__ __forceinline__ ull fmul2(ull a, ull b) {
    ull d; asm("mul.rn.f32x2 %0, %1, %2;" : "=l"(d) : "l"(a), "l"(b));
    return d;
}

// ---------------- SGEMM ----------------
#define BM 128
#define BN 128
#define BK 16

__global__ __launch_bounds__(256)
void sgemm_kernel(const float* __restrict__ A, const float* __restrict__ B,
                  float* __restrict__ Cout, int M, int N, int K,
                  int mode, int rope,
                  const float* __restrict__ cosT, const float* __restrict__ sinT)
{
    __shared__ float As[BK][BM];
    __shared__ float Bs[BK][BN];
    const int tid = threadIdx.x;
    const int tx = tid & 15, ty = tid >> 4;
    const int bm = blockIdx.y * BM, bn = blockIdx.x * BN;
    const int aRow = tid >> 2, aCol = (tid & 3) << 2;
    const int bRow = tid >> 5, bCol = (tid & 31) << 2;

    float acc[8][8];
#pragma unroll
    for (int i = 0; i < 8; i++)
#pragma unroll
        for (int j = 0; j < 8; j++) acc[i][j] = 0.f;

    for (int k0 = 0; k0 < K; k0 += BK) {
#pragma unroll
        for (int r = 0; r < 2; r++) {
            float4 va = *(const float4*)(A + (size_t)(bm + aRow + r * 64) * K + k0 + aCol);
            As[aCol + 0][aRow + r * 64] = va.x;
            As[aCol + 1][aRow + r * 64] = va.y;
            As[aCol + 2][aRow + r * 64] = va.z;
            As[aCol + 3][aRow + r * 64] = va.w;
        }
#pragma unroll
        for (int r = 0; r < 2; r++) {
            *(float4*)(&Bs[bRow + r * 8][bCol]) =
                *(const float4*)(B + (size_t)(k0 + bRow + r * 8) * N + bn + bCol);
        }
        __syncthreads();
#pragma unroll
        for (int kk = 0; kk < BK; kk++) {
            float ar[8], br[8];
#pragma unroll
            for (int i = 0; i < 4; i++) {
                ar[i] = As[kk][ty * 4 + i];
                ar[4 + i] = As[kk][64 + ty * 4 + i];
            }
#pragma unroll
            for (int j = 0; j < 4; j++) {
                br[j] = Bs[kk][tx * 4 + j];
                br[4 + j] = Bs[kk][64 + tx * 4 + j];
            }
#pragma unroll
            for (int i = 0; i < 8; i++)
#pragma unroll
                for (int j = 0; j < 8; j++) acc[i][j] += ar[i] * br[j];
        }
        __syncthreads();
    }

#pragma unroll
    for (int ig = 0; ig < 2; ig++) {
#pragma unroll
        for (int i = 0; i < 4; i++) {
            const int gr = bm + ig * 64 + ty * 4 + i;
            const int i8 = ig * 4 + i;
            const int trow = gr & (T_DIM - 1);
#pragma unroll
            for (int jg = 0; jg < 2; jg++) {
                const int cbase = bn + jg * 64 + tx * 4;
                float o0 = acc[i8][jg * 4 + 0], o1 = acc[i8][jg * 4 + 1];
                float o2 = acc[i8][jg * 4 + 2], o3 = acc[i8][jg * 4 + 3];
                if (rope) {
                    const int cmod = cbase & (C_DIM - 1);
                    const int f0 = cmod >> 1;
                    const float c0 = cosT[trow * HALF_C + f0];
                    const float s0 = sinT[trow * HALF_C + f0];
                    const float c1 = cosT[trow * HALF_C + f0 + 1];
                    const float s1 = sinT[trow * HALF_C + f0 + 1];
                    const float e0 = o0, od0 = o1, e1 = o2, od1 = o3;
                    o0 = e0 * c0 - od0 * s0;
                    o1 = e0 * s0 + od0 * c0;
                    o2 = e1 * c1 - od1 * s1;
                    o3 = e1 * s1 + od1 * c1;
                }
                if (mode == 0) {
                    float* p = Cout + (size_t)gr * N + cbase;
                    p[0] = o0; p[1] = o1; p[2] = o2; p[3] = o3;
                } else {
                    const int n = cbase >> 9;
                    const int c = cbase & (C_DIM - 1);
                    const int bb = gr >> 11;
                    float* p = Cout + ((size_t)((bb * NB + n) * T_DIM + trow)) * C_DIM + c;
                    p[0] = o0; p[1] = o1; p[2] = o2; p[3] = o3;
                }
            }
        }
    }
}

// ---------------- tiled routed flash attention (f32x2 + double buffer) ----------------
__global__ __launch_bounds__(256)
void attn_tile_kernel(const float* __restrict__ q, const float* __restrict__ k,
                      const float* __restrict__ v)
{
    __shared__ __align__(16) float Qs[2][16][129];
    __shared__ __align__(16) float Ks[2][16][68];
    __shared__ float Pp[ST][QT + 1];
    __shared__ int   Bm[ST][QT + 1];
    __shared__ float Corr[QT];

    const int tid = threadIdx.x;
    const int b = blockIdx.x / UPB;
    int u = blockIdx.x % UPB;
    int qt = 0;
    {
        int acc = 0;
        for (int j = 0; j < 64; j++) {
            int c = (j >> 3) + 1;
            if (u < acc + c) { qt = j; u -= acc; break; }
            acc += c;
        }
    }
    const int s_begin = u * 256;
    const int s_end = min(s_begin + 256, qt * 32 + 32);

    const int tq = tid >> 3, ts = tid & 7;
    const int ts8 = ts * 8;
    const int t_glob = qt * 32 + tq;
    const int warp = tid >> 5, lane = tid & 31;

    const float* kb = k + (size_t)b * T_DIM * C_DIM;
    const float* qb = q + (size_t)b * NB * T_DIM * C_DIM;
    const float* vb = v + (size_t)b * NB * T_DIM * C_DIM;

    float m = NEGINF, l = 0.f;
    ull y2[4][8];  // [a][i*2+h]: floats (i*128 + lane*4 + h*2 ..)
#pragma unroll
    for (int a = 0; a < 4; a++)
#pragma unroll
        for (int h = 0; h < 8; h++) y2[a][h] = 0ull;

    const int qrow = tid >> 1;
    const int qhalf = (tid & 1) * 8;
    const float* qsrc = qb + ((size_t)(qrow >> 5) * T_DIM + qt * 32 + (qrow & 31)) * C_DIM;
    const int krow = tid >> 2;
    const int kcol = (tid & 3) * 4;

    for (int s0 = s_begin; s0 < s_end; s0 += ST) {
        ull d2[4][4];
#pragma unroll
        for (int n = 0; n < 4; n++)
#pragma unroll
            for (int j = 0; j < 4; j++) d2[n][j] = 0ull;

        // prologue: slab 0 into buffer 0
        {
            float4 qa = *(const float4*)(qsrc + qhalf);
            float4 qc = *(const float4*)(qsrc + qhalf + 4);
            float4 kv = *(const float4*)(kb + (size_t)(s0 + krow) * C_DIM + kcol);
            Qs[0][qhalf + 0][qrow] = qa.x; Qs[0][qhalf + 1][qrow] = qa.y;
            Qs[0][qhalf + 2][qrow] = qa.z; Qs[0][qhalf + 3][qrow] = qa.w;
            Qs[0][qhalf + 4][qrow] = qc.x; Qs[0][qhalf + 5][qrow] = qc.y;
            Qs[0][qhalf + 6][qrow] = qc.z; Qs[0][qhalf + 7][qrow] = qc.w;
            Ks[0][kcol + 0][krow] = kv.x; Ks[0][kcol + 1][krow] = kv.y;
            Ks[0][kcol + 2][krow] = kv.z; Ks[0][kcol + 3][krow] = kv.w;
        }
        __syncthreads();

#pragma unroll 1
        for (int slab = 0; slab < 32; slab++) {
            const int cur = slab & 1;
            float4 nqa, nqc, nkv;
            if (slab < 31) {
                const int k0 = (slab + 1) * 16;
                nqa = *(const float4*)(qsrc + k0 + qhalf);
                nqc = *(const float4*)(qsrc + k0 + qhalf + 4);
                nkv = *(const float4*)(kb + (size_t)(s0 + krow) * C_DIM + k0 + kcol);
            }
#pragma unroll
            for (int kk = 0; kk < 16; kk++) {
                const ull p0 = pk2(Qs[cur][kk][tq]);
                const ull p1 = pk2(Qs[cur][kk][32 + tq]);
                const ull p2 = pk2(Qs[cur][kk][64 + tq]);
                const ull p3 = pk2(Qs[cur][kk][96 + tq]);
                const ulonglong2* kp = (const ulonglong2*)&Ks[cur][kk][ts8];
                const ulonglong2 kA = kp[0];
                const ulonglong2 kB = kp[1];
                d2[0][0] = ffma2(p0, kA.x, d2[0][0]); d2[0][1] = ffma2(p0, kA.y, d2[0][1]);
                d2[0][2] = ffma2(p0, kB.x, d2[0][2]); d2[0][3] = ffma2(p0, kB.y, d2[0][3]);
                d2[1][0] = ffma2(p1, kA.x, d2[1][0]); d2[1][1] = ffma2(p1, kA.y, d2[1][1]);
                d2[1][2] = ffma2(p1, kB.x, d2[1][2]); d2[1][3] = ffma2(p1, kB.y, d2[1][3]);
                d2[2][0] = ffma2(p2, kA.x, d2[2][0]); d2[2][1] = ffma2(p2, kA.y, d2[2][1]);
                d2[2][2] = ffma2(p2, kB.x, d2[2][2]); d2[2][3] = ffma2(p2, kB.y, d2[2][3]);
                d2[3][0] = ffma2(p3, kA.x, d2[3][0]); d2[3][1] = ffma2(p3, kA.y, d2[3][1]);
                d2[3][2] = ffma2(p3, kB.x, d2[3][2]); d2[3][3] = ffma2(p3, kB.y, d2[3][3]);
            }
            if (slab < 31) {
                const int nxt = cur ^ 1;
                Qs[nxt][qhalf + 0][qrow] = nqa.x; Qs[nxt][qhalf + 1][qrow] = nqa.y;
                Qs[nxt][qhalf + 2][qrow] = nqa.z; Qs[nxt][qhalf + 3][qrow] = nqa.w;
                Qs[nxt][qhalf + 4][qrow] = nqc.x; Qs[nxt][qhalf + 5][qrow] = nqc.y;
                Qs[nxt][qhalf + 6][qrow] = nqc.z; Qs[nxt][qhalf + 7][qrow] = nqc.w;
                Ks[nxt][kcol + 0][krow] = nkv.x; Ks[nxt][kcol + 1][krow] = nkv.y;
                Ks[nxt][kcol + 2][krow] = nkv.z; Ks[nxt][kcol + 3][krow] = nkv.w;
            }
            __syncthreads();
        }

        // unpack scores
        float d[4][8];
#pragma unroll
        for (int n = 0; n < 4; n++)
#pragma unroll
            for (int j = 0; j < 4; j++) upk2(d2[n][j], d[n][2 * j], d[n][2 * j + 1]);

        // routing + tile softmax
        float amax[8];
        int msk[8];
        float tmax = NEGINF;
#pragma unroll
        for (int j = 0; j < 8; j++) {
            const int sg = s0 + ts8 + j;
            const float d0 = d[0][j] * SCALE, d1 = d[1][j] * SCALE;
            const float d2v = d[2][j] * SCALE, d3 = d[3][j] * SCALE;
            float am = fmaxf(fmaxf(d0, d1), fmaxf(d2v, d3));
            int mk = (d0 == am ? 1 : 0) | (d1 == am ? 2 : 0) |
                     (d2v == am ? 4 : 0) | (d3 == am ? 8 : 0);
            if (sg > t_glob) am = NEGINF;
            amax[j] = am; msk[j] = mk;
            tmax = fmaxf(tmax, am);
        }
        tmax = fmaxf(tmax, __shfl_xor_sync(0xffffffffu, tmax, 1));
        tmax = fmaxf(tmax, __shfl_xor_sync(0xffffffffu, tmax, 2));
        tmax = fmaxf(tmax, __shfl_xor_sync(0xffffffffu, tmax, 4));
        const float nm = fmaxf(m, tmax);
        const float corr = __expf(m - nm);
        float psum = 0.f;
#pragma unroll
        for (int j = 0; j < 8; j++) {
            const float p = (amax[j] <= NEGINF) ? 0.f : __expf(amax[j] - nm);
            Pp[ts8 + j][tq] = p;
            Bm[ts8 + j][tq] = msk[j];
            psum += p;
        }
        psum += __shfl_xor_sync(0xffffffffu, psum, 1);
        psum += __shfl_xor_sync(0xffffffffu, psum, 2);
        psum += __shfl_xor_sync(0xffffffffu, psum, 4);
        l = l * corr + psum;
        m = nm;
        if (ts == 0) Corr[tq] = corr;
        __syncthreads();

        // PV (packed f32x2)
#pragma unroll
        for (int a = 0; a < 4; a++) {
            const ull cp = pk2(Corr[warp + a * 8]);
#pragma unroll
            for (int h = 0; h < 8; h++) y2[a][h] = fmul2(y2[a][h], cp);
        }
#pragma unroll 2
        for (int s = 0; s < ST; s++) {
            const float* vrow = vb + (size_t)(s0 + s) * C_DIM;
#pragma unroll
            for (int a = 0; a < 4; a++) {
                const float p = Pp[s][warp + a * 8];
                if (p != 0.f) {
                    const int mk = Bm[s][warp + a * 8];
                    const ull pp = pk2(p);
#pragma unroll
                    for (int n = 0; n < 4; n++) {
                        if (mk & (1 << n)) {
                            const float* vp = vrow + (size_t)n * T_DIM * C_DIM;
#pragma unroll
                            for (int i = 0; i < 4; i++) {
                                const ulonglong2 vv =
                                    *(const ulonglong2*)(vp + i * 128 + lane * 4);
                                y2[a][2 * i]     = ffma2(pp, vv.x, y2[a][2 * i]);
                                y2[a][2 * i + 1] = ffma2(pp, vv.y, y2[a][2 * i + 1]);
                            }
                        }
                    }
                }
            }
        }
        __syncthreads();
    }

    const int unit = blockIdx.x;
#pragma unroll
    for (int a = 0; a < 4; a++) {
        float* yp = g_ypart + ((size_t)unit * QT + (warp + a * 8)) * C_DIM;
#pragma unroll
        for (int i = 0; i < 4; i++) {
            ulonglong2 o;
            o.x = y2[a][2 * i]; o.y = y2[a][2 * i + 1];
            *(ulonglong2*)(yp + i * 128 + lane * 4) = o;
        }
    }
    if (ts == 0) {
        g_mpart[unit * QT + tq] = m;
        g_lpart[unit * QT + tq] = l;
    }
}

// ---------------- combine partials (coalesced, warp-per-row) ----------------
__global__ __launch_bounds__(256)
void combine_kernel(float* __restrict__ yout)
{
    const int blk = blockIdx.x;  // b*64 + qt
    const int b = blk >> 6, qt = blk & 63;
    const int warp = threadIdx.x >> 5, lane = threadIdx.x & 31;
    const int g = qt >> 3, r = qt & 7;
    const int base = qt + 4 * g * (g - 1) + r * g;  // prefix S(qt)
    const int nch = g + 1;
    const int ubase = b * UPB + base;

#pragma unroll 1
    for (int rr = 0; rr < 4; rr++) {
        const int qq = warp * 4 + rr;
        float mstar = NEGINF;
        for (int c = 0; c < nch; c++)
            mstar = fmaxf(mstar, g_mpart[(ubase + c) * QT + qq]);

        float ltot = 0.f;
        float4 acc[4];
#pragma unroll
        for (int i = 0; i < 4; i++) acc[i] = make_float4(0.f, 0.f, 0.f, 0.f);

        for (int c = 0; c < nch; c++) {
            const float mi = g_mpart[(ubase + c) * QT + qq];
            const float li = g_lpart[(ubase + c) * QT + qq];
            const float f = __expf(mi - mstar);
            ltot += f * li;
            const float* yp = g_ypart + ((size_t)(ubase + c) * QT + qq) * C_DIM;
#pragma unroll
            for (int i = 0; i < 4; i++) {
                const float4 vv = *(const float4*)(yp + i * 128 + lane * 4);
                acc[i].x += f * vv.x; acc[i].y += f * vv.y;
                acc[i].z += f * vv.z; acc[i].w += f * vv.w;
            }
        }
        const float inv = 1.f / ltot;
        float* out = yout + ((size_t)(b * T_DIM + qt * 32 + qq)) * C_DIM;
#pragma unroll
        for (int i = 0; i < 4; i++) {
            float4 o = make_float4(acc[i].x * inv, acc[i].y * inv,
                                   acc[i].z * inv, acc[i].w * inv);
            *(float4*)(out + i * 128 + lane * 4) = o;
        }
    }
}

// ---------------- launch ----------------
extern "C" void kernel_launch(void* const* d_in, const int* in_sizes, int n_in,
                              void* d_out, int out_size)
{
    const float* a    = (const float*)d_in[0];
    const float* x    = (const float*)d_in[1];
    const float* Wq   = (const float*)d_in[2];
    const float* Wk   = (const float*)d_in[3];
    const float* Wv   = (const float*)d_in[4];
    const float* Wo   = (const float*)d_in[5];
    const float* cosT = (const float*)d_in[6];
    const float* sinT = (const float*)d_in[7];
    float* out = (float*)d_out;

    float *qp, *vp, *kp, *yp;
    cudaGetSymbolAddress((void**)&qp, g_q);
    cudaGetSymbolAddress((void**)&vp, g_v);
    cudaGetSymbolAddress((void**)&kp, g_k);
    cudaGetSymbolAddress((void**)&yp, g_y);

    const int M = BATCH * T_DIM;
    dim3 blk(256);

    sgemm_kernel<<<dim3((NB * C_DIM) / BN, M / BM), blk>>>(
        a, Wq, qp, M, NB * C_DIM, C_DIM, 1, 1, cosT, sinT);
    sgemm_kernel<<<dim3((NB * C_DIM) / BN, M / BM), blk>>>(
        a, Wv, vp, M, NB * C_DIM, C_DIM, 1, 0, cosT, sinT);
    sgemm_kernel<<<dim3(C_DIM / BN, M / BM), blk>>>(
        x, Wk, kp, M, C_DIM, C_DIM, 0, 1, cosT, sinT);
    attn_tile_kernel<<<UNITS, 256>>>(qp, kp, vp);
    combine_kernel<<<BATCH * 64, 256>>>(yp);
    sgemm_kernel<<<dim3(C_DIM / BN, M / BM), blk>>>(
        yp, Wo, out, M, C_DIM, C_DIM, 0, 0, cosT, sinT);
}

// round 16
// speedup vs baseline: 1.1175x; 1.1175x over previous
#include <cuda_runtime.h>
#include <math.h>

#define T_DIM 2048
#define C_DIM 512
#define NB 4
#define BATCH 2
#define HALF_C 256
#define SCALE 0.044194173824159216f
#define NEGINF -1e30f

#define QT 32
#define ST 64
#define UPB 288
#define UNITS (BATCH * UPB)  // 576

typedef unsigned long long ull;

__device__ float g_q[BATCH * NB * T_DIM * C_DIM];
__device__ float g_v[BATCH * NB * T_DIM * C_DIM];
__device__ float g_k[BATCH * T_DIM * C_DIM];
__device__ float g_y[BATCH * T_DIM * C_DIM];
__device__ float g_ypart[(size_t)UNITS * QT * C_DIM];
__device__ float g_mpart[UNITS * QT];
__device__ float g_lpart[UNITS * QT];

// ---- f32x2 packed helpers (used ONLY in PV accumulate: register-neutral there) ----
__device__ __forceinline__ ull pk2(float v) {
    ull r; asm("mov.b64 %0, {%1, %1};" : "=l"(r) : "f"(v)); return r;
}
__device__ __forceinline__ ull ffma2(ull a, ull b, ull c) {
    ull d; asm("fma.rn.f32x2 %0, %1, %2, %3;" : "=l"(d) : "l"(a), "l"(b), "l"(c));
    return d;
}
__device__ __forceinline__ ull fmul2(ull a, ull b) {
    ull d; asm("mul.rn.f32x2 %0, %1, %2;" : "=l"(d) : "l"(a), "l"(b));
    return d;
}

// ---------------- SGEMM (unchanged) ----------------
#define BM 128
#define BN 128
#define BK 16

__global__ __launch_bounds__(256)
void sgemm_kernel(const float* __restrict__ A, const float* __restrict__ B,
                  float* __restrict__ Cout, int M, int N, int K,
                  int mode, int rope,
                  const float* __restrict__ cosT, const float* __restrict__ sinT)
{
    __shared__ float As[BK][BM];
    __shared__ float Bs[BK][BN];
    const int tid = threadIdx.x;
    const int tx = tid & 15, ty = tid >> 4;
    const int bm = blockIdx.y * BM, bn = blockIdx.x * BN;
    const int aRow = tid >> 2, aCol = (tid & 3) << 2;
    const int bRow = tid >> 5, bCol = (tid & 31) << 2;

    float acc[8][8];
#pragma unroll
    for (int i = 0; i < 8; i++)
#pragma unroll
        for (int j = 0; j < 8; j++) acc[i][j] = 0.f;

    for (int k0 = 0; k0 < K; k0 += BK) {
#pragma unroll
        for (int r = 0; r < 2; r++) {
            float4 va = *(const float4*)(A + (size_t)(bm + aRow + r * 64) * K + k0 + aCol);
            As[aCol + 0][aRow + r * 64] = va.x;
            As[aCol + 1][aRow + r * 64] = va.y;
            As[aCol + 2][aRow + r * 64] = va.z;
            As[aCol + 3][aRow + r * 64] = va.w;
        }
#pragma unroll
        for (int r = 0; r < 2; r++) {
            *(float4*)(&Bs[bRow + r * 8][bCol]) =
                *(const float4*)(B + (size_t)(k0 + bRow + r * 8) * N + bn + bCol);
        }
        __syncthreads();
#pragma unroll
        for (int kk = 0; kk < BK; kk++) {
            float ar[8], br[8];
#pragma unroll
            for (int i = 0; i < 4; i++) {
                ar[i] = As[kk][ty * 4 + i];
                ar[4 + i] = As[kk][64 + ty * 4 + i];
            }
#pragma unroll
            for (int j = 0; j < 4; j++) {
                br[j] = Bs[kk][tx * 4 + j];
                br[4 + j] = Bs[kk][64 + tx * 4 + j];
            }
#pragma unroll
            for (int i = 0; i < 8; i++)
#pragma unroll
                for (int j = 0; j < 8; j++) acc[i][j] += ar[i] * br[j];
        }
        __syncthreads();
    }

#pragma unroll
    for (int ig = 0; ig < 2; ig++) {
#pragma unroll
        for (int i = 0; i < 4; i++) {
            const int gr = bm + ig * 64 + ty * 4 + i;
            const int i8 = ig * 4 + i;
            const int trow = gr & (T_DIM - 1);
#pragma unroll
            for (int jg = 0; jg < 2; jg++) {
                const int cbase = bn + jg * 64 + tx * 4;
                float o0 = acc[i8][jg * 4 + 0], o1 = acc[i8][jg * 4 + 1];
                float o2 = acc[i8][jg * 4 + 2], o3 = acc[i8][jg * 4 + 3];
                if (rope) {
                    const int cmod = cbase & (C_DIM - 1);
                    const int f0 = cmod >> 1;
                    const float c0 = cosT[trow * HALF_C + f0];
                    const float s0 = sinT[trow * HALF_C + f0];
                    const float c1 = cosT[trow * HALF_C + f0 + 1];
                    const float s1 = sinT[trow * HALF_C + f0 + 1];
                    const float e0 = o0, od0 = o1, e1 = o2, od1 = o3;
                    o0 = e0 * c0 - od0 * s0;
                    o1 = e0 * s0 + od0 * c0;
                    o2 = e1 * c1 - od1 * s1;
                    o3 = e1 * s1 + od1 * c1;
                }
                if (mode == 0) {
                    float* p = Cout + (size_t)gr * N + cbase;
                    p[0] = o0; p[1] = o1; p[2] = o2; p[3] = o3;
                } else {
                    const int n = cbase >> 9;
                    const int c = cbase & (C_DIM - 1);
                    const int bb = gr >> 11;
                    float* p = Cout + ((size_t)((bb * NB + n) * T_DIM + trow)) * C_DIM + c;
                    p[0] = o0; p[1] = o1; p[2] = o2; p[3] = o3;
                }
            }
        }
    }
}

// ---------------- tiled routed flash attention (R4 score core + FFMA2 PV) ----------------
__global__ __launch_bounds__(256, 2)
void attn_tile_kernel(const float* __restrict__ q, const float* __restrict__ k,
                      const float* __restrict__ v)
{
    __shared__ float Qs[16][129];
    __shared__ float Ks[16][68];
    __shared__ float Pp[ST][QT + 1];
    __shared__ int   Bm[ST][QT + 1];
    __shared__ float Corr[QT];

    const int tid = threadIdx.x;
    const int b = blockIdx.x / UPB;
    int u = blockIdx.x % UPB;
    int qt = 0;
    {
        int acc = 0;
        for (int j = 0; j < 64; j++) {
            int c = (j >> 3) + 1;
            if (u < acc + c) { qt = j; u -= acc; break; }
            acc += c;
        }
    }
    const int s_begin = u * 256;
    const int s_end = min(s_begin + 256, qt * 32 + 32);

    const int tq = tid >> 3, ts = tid & 7;
    const int ts8 = ts * 8;
    const int t_glob = qt * 32 + tq;
    const int warp = tid >> 5, lane = tid & 31;

    const float* kb = k + (size_t)b * T_DIM * C_DIM;
    const float* qb = q + (size_t)b * NB * T_DIM * C_DIM;
    const float* vb = v + (size_t)b * NB * T_DIM * C_DIM;

    float m = NEGINF, l = 0.f;
    ull y2[4][8];  // [a][i*2+h]: floats at (i*128 + lane*4 + h*2 ..)
#pragma unroll
    for (int a = 0; a < 4; a++)
#pragma unroll
        for (int h = 0; h < 8; h++) y2[a][h] = 0ull;

    const int qrow = tid >> 1;
    const int qhalf = (tid & 1) * 8;
    const float* qsrc = qb + ((size_t)(qrow >> 5) * T_DIM + qt * 32 + (qrow & 31)) * C_DIM;
    const int krow = tid >> 2;
    const int kcol = (tid & 3) * 4;

    for (int s0 = s_begin; s0 < s_end; s0 += ST) {
        float d[4][8];
#pragma unroll
        for (int n = 0; n < 4; n++)
#pragma unroll
            for (int j = 0; j < 8; j++) d[n][j] = 0.f;

        for (int k0 = 0; k0 < C_DIM; k0 += 16) {
            float4 v0 = *(const float4*)(qsrc + k0 + qhalf);
            float4 v1 = *(const float4*)(qsrc + k0 + qhalf + 4);
            Qs[qhalf + 0][qrow] = v0.x; Qs[qhalf + 1][qrow] = v0.y;
            Qs[qhalf + 2][qrow] = v0.z; Qs[qhalf + 3][qrow] = v0.w;
            Qs[qhalf + 4][qrow] = v1.x; Qs[qhalf + 5][qrow] = v1.y;
            Qs[qhalf + 6][qrow] = v1.z; Qs[qhalf + 7][qrow] = v1.w;
            float4 kv = *(const float4*)(kb + (size_t)(s0 + krow) * C_DIM + k0 + kcol);
            Ks[kcol + 0][krow] = kv.x; Ks[kcol + 1][krow] = kv.y;
            Ks[kcol + 2][krow] = kv.z; Ks[kcol + 3][krow] = kv.w;
            __syncthreads();
#pragma unroll
            for (int kk = 0; kk < 16; kk++) {
                const float a0 = Qs[kk][tq], a1 = Qs[kk][32 + tq];
                const float a2 = Qs[kk][64 + tq], a3 = Qs[kk][96 + tq];
                const float4 b0 = *(const float4*)&Ks[kk][ts8];
                const float4 b1 = *(const float4*)&Ks[kk][ts8 + 4];
#define FM(n, an) \
    d[n][0] += an * b0.x; d[n][1] += an * b0.y; d[n][2] += an * b0.z; d[n][3] += an * b0.w; \
    d[n][4] += an * b1.x; d[n][5] += an * b1.y; d[n][6] += an * b1.z; d[n][7] += an * b1.w;
                FM(0, a0) FM(1, a1) FM(2, a2) FM(3, a3)
#undef FM
            }
            __syncthreads();
        }

        // routing + tile softmax
        float amax[8];
        int msk[8];
        float tmax = NEGINF;
#pragma unroll
        for (int j = 0; j < 8; j++) {
            const int sg = s0 + ts8 + j;
            const float d0 = d[0][j] * SCALE, d1 = d[1][j] * SCALE;
            const float d2v = d[2][j] * SCALE, d3 = d[3][j] * SCALE;
            float am = fmaxf(fmaxf(d0, d1), fmaxf(d2v, d3));
            int mk = (d0 == am ? 1 : 0) | (d1 == am ? 2 : 0) |
                     (d2v == am ? 4 : 0) | (d3 == am ? 8 : 0);
            if (sg > t_glob) am = NEGINF;
            amax[j] = am; msk[j] = mk;
            tmax = fmaxf(tmax, am);
        }
        tmax = fmaxf(tmax, __shfl_xor_sync(0xffffffffu, tmax, 1));
        tmax = fmaxf(tmax, __shfl_xor_sync(0xffffffffu, tmax, 2));
        tmax = fmaxf(tmax, __shfl_xor_sync(0xffffffffu, tmax, 4));
        const float nm = fmaxf(m, tmax);
        const float corr = __expf(m - nm);
        float psum = 0.f;
#pragma unroll
        for (int j = 0; j < 8; j++) {
            const float p = (amax[j] <= NEGINF) ? 0.f : __expf(amax[j] - nm);
            Pp[ts8 + j][tq] = p;
            Bm[ts8 + j][tq] = msk[j];
            psum += p;
        }
        psum += __shfl_xor_sync(0xffffffffu, psum, 1);
        psum += __shfl_xor_sync(0xffffffffu, psum, 2);
        psum += __shfl_xor_sync(0xffffffffu, psum, 4);
        l = l * corr + psum;
        m = nm;
        if (ts == 0) Corr[tq] = corr;
        __syncthreads();

        // PV (packed f32x2 accumulate — register-neutral)
#pragma unroll
        for (int a = 0; a < 4; a++) {
            const ull cp = pk2(Corr[warp + a * 8]);
#pragma unroll
            for (int h = 0; h < 8; h++) y2[a][h] = fmul2(y2[a][h], cp);
        }
        for (int s = 0; s < ST; s++) {
            const float* vrow = vb + (size_t)(s0 + s) * C_DIM;
#pragma unroll
            for (int a = 0; a < 4; a++) {
                const float p = Pp[s][warp + a * 8];
                if (p != 0.f) {
                    const int mk = Bm[s][warp + a * 8];
                    const ull pp = pk2(p);
#pragma unroll
                    for (int n = 0; n < 4; n++) {
                        if (mk & (1 << n)) {
                            const float* vp = vrow + (size_t)n * T_DIM * C_DIM;
#pragma unroll
                            for (int i = 0; i < 4; i++) {
                                const ulonglong2 vv =
                                    *(const ulonglong2*)(vp + i * 128 + lane * 4);
                                y2[a][2 * i]     = ffma2(pp, vv.x, y2[a][2 * i]);
                                y2[a][2 * i + 1] = ffma2(pp, vv.y, y2[a][2 * i + 1]);
                            }
                        }
                    }
                }
            }
        }
        __syncthreads();
    }

    const int unit = blockIdx.x;
#pragma unroll
    for (int a = 0; a < 4; a++) {
        float* yp = g_ypart + ((size_t)unit * QT + (warp + a * 8)) * C_DIM;
#pragma unroll
        for (int i = 0; i < 4; i++) {
            ulonglong2 o;
            o.x = y2[a][2 * i]; o.y = y2[a][2 * i + 1];
            *(ulonglong2*)(yp + i * 128 + lane * 4) = o;
        }
    }
    if (ts == 0) {
        g_mpart[unit * QT + tq] = m;
        g_lpart[unit * QT + tq] = l;
    }
}

// ---------------- combine partials (coalesced, warp-per-row) ----------------
__global__ __launch_bounds__(256)
void combine_kernel(float* __restrict__ yout)
{
    const int blk = blockIdx.x;  // b*64 + qt
    const int b = blk >> 6, qt = blk & 63;
    const int warp = threadIdx.x >> 5, lane = threadIdx.x & 31;
    const int g = qt >> 3, r = qt & 7;
    const int base = qt + 4 * g * (g - 1) + r * g;  // prefix S(qt)
    const int nch = g + 1;
    const int ubase = b * UPB + base;

#pragma unroll 1
    for (int rr = 0; rr < 4; rr++) {
        const int qq = warp * 4 + rr;
        float mstar = NEGINF;
        for (int c = 0; c < nch; c++)
            mstar = fmaxf(mstar, g_mpart[(ubase + c) * QT + qq]);

        float ltot = 0.f;
        float4 acc[4];
#pragma unroll
        for (int i = 0; i < 4; i++) acc[i] = make_float4(0.f, 0.f, 0.f, 0.f);

        for (int c = 0; c < nch; c++) {
            const float mi = g_mpart[(ubase + c) * QT + qq];
            const float li = g_lpart[(ubase + c) * QT + qq];
            const float f = __expf(mi - mstar);
            ltot += f * li;
            const float* yp = g_ypart + ((size_t)(ubase + c) * QT + qq) * C_DIM;
#pragma unroll
            for (int i = 0; i < 4; i++) {
                const float4 vv = *(const float4*)(yp + i * 128 + lane * 4);
                acc[i].x += f * vv.x; acc[i].y += f * vv.y;
                acc[i].z += f * vv.z; acc[i].w += f * vv.w;
            }
        }
        const float inv = 1.f / ltot;
        float* out = yout + ((size_t)(b * T_DIM + qt * 32 + qq)) * C_DIM;
#pragma unroll
        for (int i = 0; i < 4; i++) {
            float4 o = make_float4(acc[i].x * inv, acc[i].y * inv,
                                   acc[i].z * inv, acc[i].w * inv);
            *(float4*)(out + i * 128 + lane * 4) = o;
        }
    }
}

// ---------------- launch ----------------
extern "C" void kernel_launch(void* const* d_in, const int* in_sizes, int n_in,
                              void* d_out, int out_size)
{
    const float* a    = (const float*)d_in[0];
    const float* x    = (const float*)d_in[1];
    const float* Wq   = (const float*)d_in[2];
    const float* Wk   = (const float*)d_in[3];
    const float* Wv   = (const float*)d_in[4];
    const float* Wo   = (const float*)d_in[5];
    const float* cosT = (const float*)d_in[6];
    const float* sinT = (const float*)d_in[7];
    float* out = (float*)d_out;

    float *qp, *vp, *kp, *yp;
    cudaGetSymbolAddress((void**)&qp, g_q);
    cudaGetSymbolAddress((void**)&vp, g_v);
    cudaGetSymbolAddress((void**)&kp, g_k);
    cudaGetSymbolAddress((void**)&yp, g_y);

    const int M = BATCH * T_DIM;
    dim3 blk(256);

    sgemm_kernel<<<dim3((NB * C_DIM) / BN, M / BM), blk>>>(
        a, Wq, qp, M, NB * C_DIM, C_DIM, 1, 1, cosT, sinT);
    sgemm_kernel<<<dim3((NB * C_DIM) / BN, M / BM), blk>>>(
        a, Wv, vp, M, NB * C_DIM, C_DIM, 1, 0, cosT, sinT);
    sgemm_kernel<<<dim3(C_DIM / BN, M / BM), blk>>>(
        x, Wk, kp, M, C_DIM, C_DIM, 0, 1, cosT, sinT);
    attn_tile_kernel<<<UNITS, 256>>>(qp, kp, vp);
    combine_kernel<<<BATCH * 64, 256>>>(yp);
    sgemm_kernel<<<dim3(C_DIM / BN, M / BM), blk>>>(
        yp, Wo, out, M, C_DIM, C_DIM, 0, 0, cosT, sinT);
}